// round 3
// baseline (speedup 1.0000x reference)
#include <cuda_runtime.h>

#define NN 100000
#define NE 800000
#define HC 512
#define IND 64
#define SCAN_B 1024
#define NBLK ((NN + SCAN_B - 1) / SCAN_B)   // 98

// ---------------- device scratch (no allocations allowed) ----------------
__device__ float g_xl[(size_t)NN * HC];   // 204.8 MB
__device__ float g_xr[(size_t)NN * HC];   // 204.8 MB
__device__ int   g_count[NN];
__device__ int   g_off[NN + 1];
__device__ int   g_cursor[NN];
__device__ int   g_srcs[NE];
__device__ int   g_bsum[NBLK];

// ---------------- GEMM: Y[N,512] = X[N,64] @ W[64,512] ----------------
// WHICH=0 -> writes g_xl, WHICH=1 -> writes g_xr (no host symbol queries)
template <int WHICH>
__global__ __launch_bounds__(256) void gemm_kernel(const float* __restrict__ X,
                                                   const float* __restrict__ W) {
    float* __restrict__ Y = WHICH ? g_xr : g_xl;
    __shared__ float As[32][64];    // row-major x tile
    __shared__ float Bs[64][128];   // row-major W tile
    const int rb  = blockIdx.x * 32;
    const int cb  = blockIdx.y * 128;
    const int tid = threadIdx.x;

    // load x tile: 32x64 = 512 float4, 2 per thread
#pragma unroll
    for (int i = 0; i < 2; i++) {
        int idx = tid + i * 256;
        int r = idx >> 4, c4 = idx & 15;
        float4 v = *(const float4*)(X + (size_t)(rb + r) * IND + c4 * 4);
        *(float4*)(&As[r][c4 * 4]) = v;
    }
    // load W tile: 64x128 = 2048 float4, 8 per thread
#pragma unroll
    for (int i = 0; i < 8; i++) {
        int idx = tid + i * 256;
        int r = idx >> 5, c4 = idx & 31;
        float4 v = *(const float4*)(W + (size_t)r * HC + cb + c4 * 4);
        *(float4*)(&Bs[r][c4 * 4]) = v;
    }
    __syncthreads();

    const int rx = tid & 31;   // col group (x4)
    const int ry = tid >> 5;   // row group (x4)
    float acc[4][4] = {};
#pragma unroll
    for (int k = 0; k < 64; k++) {
        float a0 = As[ry * 4 + 0][k];
        float a1 = As[ry * 4 + 1][k];
        float a2 = As[ry * 4 + 2][k];
        float a3 = As[ry * 4 + 3][k];
        float4 b = *(const float4*)(&Bs[k][rx * 4]);
        acc[0][0] = fmaf(a0, b.x, acc[0][0]); acc[0][1] = fmaf(a0, b.y, acc[0][1]);
        acc[0][2] = fmaf(a0, b.z, acc[0][2]); acc[0][3] = fmaf(a0, b.w, acc[0][3]);
        acc[1][0] = fmaf(a1, b.x, acc[1][0]); acc[1][1] = fmaf(a1, b.y, acc[1][1]);
        acc[1][2] = fmaf(a1, b.z, acc[1][2]); acc[1][3] = fmaf(a1, b.w, acc[1][3]);
        acc[2][0] = fmaf(a2, b.x, acc[2][0]); acc[2][1] = fmaf(a2, b.y, acc[2][1]);
        acc[2][2] = fmaf(a2, b.z, acc[2][2]); acc[2][3] = fmaf(a2, b.w, acc[2][3]);
        acc[3][0] = fmaf(a3, b.x, acc[3][0]); acc[3][1] = fmaf(a3, b.y, acc[3][1]);
        acc[3][2] = fmaf(a3, b.z, acc[3][2]); acc[3][3] = fmaf(a3, b.w, acc[3][3]);
    }
#pragma unroll
    for (int i = 0; i < 4; i++) {
        float4 o = make_float4(acc[i][0], acc[i][1], acc[i][2], acc[i][3]);
        *(float4*)(Y + (size_t)(rb + ry * 4 + i) * HC + cb + rx * 4) = o;
    }
}

// ---------------- CSR build ----------------
__global__ void zero_count_kernel() {
    int i = blockIdx.x * blockDim.x + threadIdx.x;
    if (i < NN) g_count[i] = 0;
}

__global__ void hist_kernel(const int* __restrict__ dst) {
    int e = blockIdx.x * blockDim.x + threadIdx.x;
    if (e < NE) atomicAdd(&g_count[dst[e]], 1);
}

__global__ __launch_bounds__(SCAN_B) void scan_block_kernel() {
    __shared__ int sm[SCAN_B];
    int i = blockIdx.x * SCAN_B + threadIdx.x;
    int v = (i < NN) ? g_count[i] : 0;
    sm[threadIdx.x] = v;
    __syncthreads();
    for (int off = 1; off < SCAN_B; off <<= 1) {
        int t = (threadIdx.x >= off) ? sm[threadIdx.x - off] : 0;
        __syncthreads();
        sm[threadIdx.x] += t;
        __syncthreads();
    }
    if (i < NN) g_off[i] = sm[threadIdx.x] - v;   // block-local exclusive
    if (threadIdx.x == SCAN_B - 1) g_bsum[blockIdx.x] = sm[SCAN_B - 1];
}

__global__ void scan_sums_kernel() {
    if (threadIdx.x == 0 && blockIdx.x == 0) {
        int s = 0;
        for (int b = 0; b < NBLK; b++) { int v = g_bsum[b]; g_bsum[b] = s; s += v; }
    }
}

__global__ __launch_bounds__(SCAN_B) void scan_add_kernel() {
    int i = blockIdx.x * SCAN_B + threadIdx.x;
    if (i < NN) {
        int o = g_off[i] + g_bsum[blockIdx.x];
        g_off[i] = o;
        g_cursor[i] = o;
    }
    if (i == 0) g_off[NN] = NE;
}

__global__ void scatter_kernel(const int* __restrict__ src,
                               const int* __restrict__ dst) {
    int e = blockIdx.x * blockDim.x + threadIdx.x;
    if (e < NE) {
        int d = dst[e];
        int pos = atomicAdd(&g_cursor[d], 1);
        g_srcs[pos] = src[e];
    }
}

// ---------------- fused node kernel: online softmax + aggregate ----------------
// one warp per destination node; 16 features per lane; head = lane>>2
__global__ __launch_bounds__(256) void node_kernel(const float* __restrict__ att,
                                                   const float* __restrict__ bias,
                                                   float* __restrict__ out) {
    int gw = (blockIdx.x * 256 + threadIdx.x) >> 5;
    int lane = threadIdx.x & 31;
    if (gw >= NN) return;
    const int base = lane * 16;

    const float* xrp = g_xr + (size_t)gw * HC + base;
    float4 xr0 = *(const float4*)(xrp + 0);
    float4 xr1 = *(const float4*)(xrp + 4);
    float4 xr2 = *(const float4*)(xrp + 8);
    float4 xr3 = *(const float4*)(xrp + 12);
    float4 at0 = *(const float4*)(att + base + 0);
    float4 at1 = *(const float4*)(att + base + 4);
    float4 at2 = *(const float4*)(att + base + 8);
    float4 at3 = *(const float4*)(att + base + 12);

    int p0 = g_off[gw];
    int p1 = g_off[gw + 1];

    float acc[16];
#pragma unroll
    for (int t = 0; t < 16; t++) acc[t] = 0.f;
    float denom = 0.f;

    if (p0 < p1) {
        const float* xlp = g_xl + (size_t)g_srcs[p0] * HC + base;
        float4 c0 = *(const float4*)(xlp + 0);
        float4 c1 = *(const float4*)(xlp + 4);
        float4 c2 = *(const float4*)(xlp + 8);
        float4 c3 = *(const float4*)(xlp + 12);

        for (int p = p0; p < p1; p++) {
            // prefetch next edge's xl row (last iter reloads current: L1 hit)
            int pn = (p + 1 < p1) ? (p + 1) : p;
            const float* np = g_xl + (size_t)g_srcs[pn] * HC + base;
            float4 n0 = *(const float4*)(np + 0);
            float4 n1 = *(const float4*)(np + 4);
            float4 n2 = *(const float4*)(np + 8);
            float4 n3 = *(const float4*)(np + 12);

            float part = 0.f;
#define TERM(cv, xv, av) { float s_ = (cv) + (xv); float l_ = fmaxf(s_, 0.2f * s_); part = fmaf((av), l_, part); }
            TERM(c0.x, xr0.x, at0.x) TERM(c0.y, xr0.y, at0.y) TERM(c0.z, xr0.z, at0.z) TERM(c0.w, xr0.w, at0.w)
            TERM(c1.x, xr1.x, at1.x) TERM(c1.y, xr1.y, at1.y) TERM(c1.z, xr1.z, at1.z) TERM(c1.w, xr1.w, at1.w)
            TERM(c2.x, xr2.x, at2.x) TERM(c2.y, xr2.y, at2.y) TERM(c2.z, xr2.z, at2.z) TERM(c2.w, xr2.w, at2.w)
            TERM(c3.x, xr3.x, at3.x) TERM(c3.y, xr3.y, at3.y) TERM(c3.z, xr3.z, at3.z) TERM(c3.w, xr3.w, at3.w)
#undef TERM
            // reduce over the 4 lanes of this head group -> e_h
            part += __shfl_xor_sync(0xffffffffu, part, 1);
            part += __shfl_xor_sync(0xffffffffu, part, 2);
            // online (max-free) softmax accumulation: alpha invariant to max-shift,
            // |e| <= ~6 so exp() is safe in fp32
            float ex = __expf(part);
            denom += ex;
            acc[0]  = fmaf(ex, c0.x, acc[0]);  acc[1]  = fmaf(ex, c0.y, acc[1]);
            acc[2]  = fmaf(ex, c0.z, acc[2]);  acc[3]  = fmaf(ex, c0.w, acc[3]);
            acc[4]  = fmaf(ex, c1.x, acc[4]);  acc[5]  = fmaf(ex, c1.y, acc[5]);
            acc[6]  = fmaf(ex, c1.z, acc[6]);  acc[7]  = fmaf(ex, c1.w, acc[7]);
            acc[8]  = fmaf(ex, c2.x, acc[8]);  acc[9]  = fmaf(ex, c2.y, acc[9]);
            acc[10] = fmaf(ex, c2.z, acc[10]); acc[11] = fmaf(ex, c2.w, acc[11]);
            acc[12] = fmaf(ex, c3.x, acc[12]); acc[13] = fmaf(ex, c3.y, acc[13]);
            acc[14] = fmaf(ex, c3.z, acc[14]); acc[15] = fmaf(ex, c3.w, acc[15]);
            c0 = n0; c1 = n1; c2 = n2; c3 = n3;
        }
    }

    float inv = 1.0f / (denom + 1e-16f);
    float4 b0 = *(const float4*)(bias + base + 0);
    float4 b1 = *(const float4*)(bias + base + 4);
    float4 b2 = *(const float4*)(bias + base + 8);
    float4 b3 = *(const float4*)(bias + base + 12);
    float* op = out + (size_t)gw * HC + base;
    *(float4*)(op + 0)  = make_float4(acc[0] * inv + b0.x,  acc[1] * inv + b0.y,
                                      acc[2] * inv + b0.z,  acc[3] * inv + b0.w);
    *(float4*)(op + 4)  = make_float4(acc[4] * inv + b1.x,  acc[5] * inv + b1.y,
                                      acc[6] * inv + b1.z,  acc[7] * inv + b1.w);
    *(float4*)(op + 8)  = make_float4(acc[8] * inv + b2.x,  acc[9] * inv + b2.y,
                                      acc[10] * inv + b2.z, acc[11] * inv + b2.w);
    *(float4*)(op + 12) = make_float4(acc[12] * inv + b3.x, acc[13] * inv + b3.y,
                                      acc[14] * inv + b3.z, acc[15] * inv + b3.w);
}

// ---------------- launch ----------------
extern "C" void kernel_launch(void* const* d_in, const int* in_sizes, int n_in,
                              void* d_out, int out_size) {
    const float* x    = (const float*)d_in[0];
    const int*   ei   = (const int*)d_in[1];   // [2, NE] int32 (JAX x64 disabled)
    const float* W_l  = (const float*)d_in[2];
    const float* W_r  = (const float*)d_in[3];
    const float* att  = (const float*)d_in[4];
    const float* bias = (const float*)d_in[5];
    float*       out  = (float*)d_out;

    const int* src = ei;
    const int* dst = ei + NE;

    dim3 ggrid(NN / 32, HC / 128);
    gemm_kernel<0><<<ggrid, 256>>>(x, W_l);
    gemm_kernel<1><<<ggrid, 256>>>(x, W_r);

    zero_count_kernel<<<(NN + 255) / 256, 256>>>();
    hist_kernel<<<(NE + 255) / 256, 256>>>(dst);
    scan_block_kernel<<<NBLK, SCAN_B>>>();
    scan_sums_kernel<<<1, 32>>>();
    scan_add_kernel<<<NBLK, SCAN_B>>>();
    scatter_kernel<<<(NE + 255) / 256, 256>>>(src, dst);

    node_kernel<<<(NN * 32 + 255) / 256, 256>>>(att, bias, out);
}

// round 4
// speedup vs baseline: 1.7238x; 1.7238x over previous
#include <cuda_runtime.h>
#include <cuda_fp16.h>
#include <mma.h>

using namespace nvcuda;

#define NN 100000
#define NE 800000
#define HC 512
#define IND 64
#define SCAN_B 1024
#define NBLK ((NN + SCAN_B - 1) / SCAN_B)   // 98

// ---------------- device scratch (no allocations allowed) ----------------
__device__ __half g_xl[(size_t)NN * HC];     // 102.4 MB
__device__ __half g_xr[(size_t)NN * HC];     // 102.4 MB
__device__ __half g_xh[(size_t)NN * IND];    // x in fp16, 12.8 MB
__device__ __half g_wh[2][IND * HC];         // W_l, W_r fp16
__device__ int    g_count[NN];
__device__ int    g_off[NN + 1];
__device__ int    g_cursor[NN];
__device__ int    g_srcs[NE];
__device__ int    g_bsum[NBLK];

// ---------------- fp32 -> fp16 conversions ----------------
__global__ void convert_x_kernel(const float* __restrict__ x) {
    int i = blockIdx.x * blockDim.x + threadIdx.x;
    if (i < NN * IND) g_xh[i] = __float2half(x[i]);
}
__global__ void convert_w_kernel(const float* __restrict__ Wl,
                                 const float* __restrict__ Wr) {
    int i = blockIdx.x * blockDim.x + threadIdx.x;
    if (i < IND * HC) {
        g_wh[0][i] = __float2half(Wl[i]);
        g_wh[1][i] = __float2half(Wr[i]);
    }
}

// ---------------- HMMA GEMM: Y[N,512] = Xh[N,64] @ Wh[64,512], fp16 out ----------------
// block = 256 thr (8 warps), tile = 128 rows x 64 cols; warp w -> rows [16w,16w+16)
#define A_LD 80            // halves per smem row (64 + 16 skew)
#define B_LD 80
#define C_LD 72            // floats per smem row (64 + 8 skew), 288B = 32B-aligned
#define SMEM_BYTES 36864   // max(128*80*2 + 64*80*2 = 30720, 128*72*4 = 36864)

template <int WHICH>
__global__ __launch_bounds__(256) void gemm_kernel() {
    __half* __restrict__ Y = WHICH ? g_xr : g_xl;
    const __half* __restrict__ W = g_wh[WHICH];
    __shared__ __align__(32) unsigned char smem[SMEM_BYTES];
    __half* As = (__half*)smem;                    // [128][A_LD]
    __half* Bs = (__half*)(smem + 128 * A_LD * 2); // [64][B_LD]

    const int rb  = blockIdx.x * 128;
    const int cb  = blockIdx.y * 64;
    const int tid = threadIdx.x;
    const int wid = tid >> 5;

    // load A tile: 128x64 halves, 8 halves (16B) per ld, 4 per thread
#pragma unroll
    for (int i = 0; i < 4; i++) {
        int idx = tid + i * 256;
        int r = idx >> 3, c8 = idx & 7;
        uint4 v = make_uint4(0, 0, 0, 0);
        if (rb + r < NN)
            v = *(const uint4*)(g_xh + (size_t)(rb + r) * IND + c8 * 8);
        *(uint4*)(As + r * A_LD + c8 * 8) = v;
    }
    // load B tile: 64x64 halves, 2 per thread
#pragma unroll
    for (int i = 0; i < 2; i++) {
        int idx = tid + i * 256;
        int r = idx >> 3, c8 = idx & 7;
        uint4 v = *(const uint4*)(W + (size_t)r * HC + cb + c8 * 8);
        *(uint4*)(Bs + r * B_LD + c8 * 8) = v;
    }
    __syncthreads();

    wmma::fragment<wmma::accumulator, 16, 16, 16, float> acc[4];
#pragma unroll
    for (int c = 0; c < 4; c++) wmma::fill_fragment(acc[c], 0.0f);

#pragma unroll
    for (int k = 0; k < 4; k++) {
        wmma::fragment<wmma::matrix_a, 16, 16, 16, __half, wmma::row_major> af;
        wmma::load_matrix_sync(af, As + (wid * 16) * A_LD + k * 16, A_LD);
#pragma unroll
        for (int c = 0; c < 4; c++) {
            wmma::fragment<wmma::matrix_b, 16, 16, 16, __half, wmma::row_major> bf;
            wmma::load_matrix_sync(bf, Bs + (k * 16) * B_LD + c * 16, B_LD);
            wmma::mma_sync(acc[c], af, bf, acc[c]);
        }
    }
    __syncthreads();   // done reading As/Bs; reuse smem for C staging

    float* Cs = (float*)smem;                      // [128][C_LD]
#pragma unroll
    for (int c = 0; c < 4; c++)
        wmma::store_matrix_sync(Cs + (wid * 16) * C_LD + c * 16, acc[c],
                                C_LD, wmma::mem_row_major);
    __syncthreads();

    // write out as fp16: 128x64 = 4096 half2, 16 per thread
#pragma unroll
    for (int i = 0; i < 16; i++) {
        int idx = tid + i * 256;
        int r = idx >> 5, c2 = idx & 31;
        if (rb + r < NN) {
            float a = Cs[r * C_LD + c2 * 2];
            float b = Cs[r * C_LD + c2 * 2 + 1];
            *(__half2*)(Y + (size_t)(rb + r) * HC + cb + c2 * 2) =
                __floats2half2_rn(a, b);
        }
    }
}

// ---------------- CSR build ----------------
__global__ void zero_count_kernel() {
    int i = blockIdx.x * blockDim.x + threadIdx.x;
    if (i < NN) g_count[i] = 0;
}

__global__ void hist_kernel(const int* __restrict__ dst) {
    int e = blockIdx.x * blockDim.x + threadIdx.x;
    if (e < NE) atomicAdd(&g_count[dst[e]], 1);
}

__global__ __launch_bounds__(SCAN_B) void scan_block_kernel() {
    __shared__ int sm[SCAN_B];
    int i = blockIdx.x * SCAN_B + threadIdx.x;
    int v = (i < NN) ? g_count[i] : 0;
    sm[threadIdx.x] = v;
    __syncthreads();
    for (int off = 1; off < SCAN_B; off <<= 1) {
        int t = (threadIdx.x >= off) ? sm[threadIdx.x - off] : 0;
        __syncthreads();
        sm[threadIdx.x] += t;
        __syncthreads();
    }
    if (i < NN) g_off[i] = sm[threadIdx.x] - v;   // block-local exclusive
    if (threadIdx.x == SCAN_B - 1) g_bsum[blockIdx.x] = sm[SCAN_B - 1];
}

__global__ void scan_sums_kernel() {
    if (threadIdx.x == 0 && blockIdx.x == 0) {
        int s = 0;
        for (int b = 0; b < NBLK; b++) { int v = g_bsum[b]; g_bsum[b] = s; s += v; }
    }
}

__global__ __launch_bounds__(SCAN_B) void scan_add_kernel() {
    int i = blockIdx.x * SCAN_B + threadIdx.x;
    if (i < NN) {
        int o = g_off[i] + g_bsum[blockIdx.x];
        g_off[i] = o;
        g_cursor[i] = o;
    }
    if (i == 0) g_off[NN] = NE;
}

__global__ void scatter_kernel(const int* __restrict__ src,
                               const int* __restrict__ dst) {
    int e = blockIdx.x * blockDim.x + threadIdx.x;
    if (e < NE) {
        int d = dst[e];
        int pos = atomicAdd(&g_cursor[d], 1);
        g_srcs[pos] = src[e];
    }
}

// ---------------- fused node kernel: online softmax + aggregate ----------------
// one warp per destination node; 16 features (fp16) per lane; head = lane>>2
__device__ __forceinline__ float2 h2f(unsigned int u) {
    __half2 h = *reinterpret_cast<__half2*>(&u);
    return __half22float2(h);
}

__global__ __launch_bounds__(256) void node_kernel(const float* __restrict__ att,
                                                   const float* __restrict__ bias,
                                                   float* __restrict__ out) {
    int gw = (blockIdx.x * 256 + threadIdx.x) >> 5;
    int lane = threadIdx.x & 31;
    if (gw >= NN) return;
    const int base = lane * 16;

    // xr row (fp16 -> fp32 once)
    const __half* xrp = g_xr + (size_t)gw * HC + base;
    uint4 xu0 = *(const uint4*)(xrp);
    uint4 xu1 = *(const uint4*)(xrp + 8);
    float2 xr0 = h2f(xu0.x), xr1 = h2f(xu0.y), xr2 = h2f(xu0.z), xr3 = h2f(xu0.w);
    float2 xr4 = h2f(xu1.x), xr5 = h2f(xu1.y), xr6 = h2f(xu1.z), xr7 = h2f(xu1.w);

    float4 at0 = *(const float4*)(att + base + 0);
    float4 at1 = *(const float4*)(att + base + 4);
    float4 at2 = *(const float4*)(att + base + 8);
    float4 at3 = *(const float4*)(att + base + 12);

    int p0 = g_off[gw];
    int p1 = g_off[gw + 1];

    float acc[16];
#pragma unroll
    for (int t = 0; t < 16; t++) acc[t] = 0.f;
    float denom = 0.f;

    if (p0 < p1) {
        const __half* xlp = g_xl + (size_t)g_srcs[p0] * HC + base;
        uint4 c0 = *(const uint4*)(xlp);
        uint4 c1 = *(const uint4*)(xlp + 8);

        for (int p = p0; p < p1; p++) {
            // prefetch next edge's xl row (last iter reloads current: L1 hit)
            int pn = (p + 1 < p1) ? (p + 1) : p;
            const __half* np = g_xl + (size_t)g_srcs[pn] * HC + base;
            uint4 n0 = *(const uint4*)(np);
            uint4 n1 = *(const uint4*)(np + 8);

            float2 f0 = h2f(c0.x), f1 = h2f(c0.y), f2 = h2f(c0.z), f3 = h2f(c0.w);
            float2 f4 = h2f(c1.x), f5 = h2f(c1.y), f6 = h2f(c1.z), f7 = h2f(c1.w);

            float part = 0.f;
#define TERM(cv, xv, av) { float s_ = (cv) + (xv); float l_ = fmaxf(s_, 0.2f * s_); part = fmaf((av), l_, part); }
            TERM(f0.x, xr0.x, at0.x) TERM(f0.y, xr0.y, at0.y) TERM(f1.x, xr1.x, at0.z) TERM(f1.y, xr1.y, at0.w)
            TERM(f2.x, xr2.x, at1.x) TERM(f2.y, xr2.y, at1.y) TERM(f3.x, xr3.x, at1.z) TERM(f3.y, xr3.y, at1.w)
            TERM(f4.x, xr4.x, at2.x) TERM(f4.y, xr4.y, at2.y) TERM(f5.x, xr5.x, at2.z) TERM(f5.y, xr5.y, at2.w)
            TERM(f6.x, xr6.x, at3.x) TERM(f6.y, xr6.y, at3.y) TERM(f7.x, xr7.x, at3.z) TERM(f7.y, xr7.y, at3.w)
#undef TERM
            // reduce over the 4 lanes of this head group -> e_h
            part += __shfl_xor_sync(0xffffffffu, part, 1);
            part += __shfl_xor_sync(0xffffffffu, part, 2);
            // max-free online softmax: |e| small, fp32 exp safe
            float ex = __expf(part);
            denom += ex;
            acc[0]  = fmaf(ex, f0.x, acc[0]);  acc[1]  = fmaf(ex, f0.y, acc[1]);
            acc[2]  = fmaf(ex, f1.x, acc[2]);  acc[3]  = fmaf(ex, f1.y, acc[3]);
            acc[4]  = fmaf(ex, f2.x, acc[4]);  acc[5]  = fmaf(ex, f2.y, acc[5]);
            acc[6]  = fmaf(ex, f3.x, acc[6]);  acc[7]  = fmaf(ex, f3.y, acc[7]);
            acc[8]  = fmaf(ex, f4.x, acc[8]);  acc[9]  = fmaf(ex, f4.y, acc[9]);
            acc[10] = fmaf(ex, f5.x, acc[10]); acc[11] = fmaf(ex, f5.y, acc[11]);
            acc[12] = fmaf(ex, f6.x, acc[12]); acc[13] = fmaf(ex, f6.y, acc[13]);
            acc[14] = fmaf(ex, f7.x, acc[14]); acc[15] = fmaf(ex, f7.y, acc[15]);
            c0 = n0; c1 = n1;
        }
    }

    float inv = 1.0f / (denom + 1e-16f);
    float4 b0 = *(const float4*)(bias + base + 0);
    float4 b1 = *(const float4*)(bias + base + 4);
    float4 b2 = *(const float4*)(bias + base + 8);
    float4 b3 = *(const float4*)(bias + base + 12);
    float* op = out + (size_t)gw * HC + base;
    *(float4*)(op + 0)  = make_float4(acc[0] * inv + b0.x,  acc[1] * inv + b0.y,
                                      acc[2] * inv + b0.z,  acc[3] * inv + b0.w);
    *(float4*)(op + 4)  = make_float4(acc[4] * inv + b1.x,  acc[5] * inv + b1.y,
                                      acc[6] * inv + b1.z,  acc[7] * inv + b1.w);
    *(float4*)(op + 8)  = make_float4(acc[8] * inv + b2.x,  acc[9] * inv + b2.y,
                                      acc[10] * inv + b2.z, acc[11] * inv + b2.w);
    *(float4*)(op + 12) = make_float4(acc[12] * inv + b3.x, acc[13] * inv + b3.y,
                                      acc[14] * inv + b3.z, acc[15] * inv + b3.w);
}

// ---------------- launch ----------------
extern "C" void kernel_launch(void* const* d_in, const int* in_sizes, int n_in,
                              void* d_out, int out_size) {
    const float* x    = (const float*)d_in[0];
    const int*   ei   = (const int*)d_in[1];   // [2, NE] int32 (JAX x64 disabled)
    const float* W_l  = (const float*)d_in[2];
    const float* W_r  = (const float*)d_in[3];
    const float* att  = (const float*)d_in[4];
    const float* bias = (const float*)d_in[5];
    float*       out  = (float*)d_out;

    const int* src = ei;
    const int* dst = ei + NE;

    convert_x_kernel<<<(NN * IND + 255) / 256, 256>>>(x);
    convert_w_kernel<<<(IND * HC + 255) / 256, 256>>>(W_l, W_r);

    dim3 ggrid((NN + 127) / 128, HC / 64);
    gemm_kernel<0><<<ggrid, 256>>>();
    gemm_kernel<1><<<ggrid, 256>>>();

    zero_count_kernel<<<(NN + 255) / 256, 256>>>();
    hist_kernel<<<(NE + 255) / 256, 256>>>(dst);
    scan_block_kernel<<<NBLK, SCAN_B>>>();
    scan_sums_kernel<<<1, 32>>>();
    scan_add_kernel<<<NBLK, SCAN_B>>>();
    scatter_kernel<<<(NE + 255) / 256, 256>>>(src, dst);

    node_kernel<<<(NN * 32 + 255) / 256, 256>>>(att, bias, out);
}